// round 2
// baseline (speedup 1.0000x reference)
#include <cuda_runtime.h>
#include <cuda_bf16.h>
#include <cstdint>

// Problem constants: B=2, S=2048, H=1024, N=16, HN=64
#define BB 2
#define SS 2048
#define HH 1024
#define NH 16
#define HD 64
#define MROWS (BB*SS)          // 4096
#define QKV_N (3*HH)           // 3072

// Device scratch (allocation-free rule -> __device__ globals)
__device__ float g_q[BB*NH*SS*HD];    // [b,n,s,d], pre-scaled by 1/sqrt(64)
__device__ float g_k[BB*NH*SS*HD];
__device__ float g_v[BB*NH*SS*HD];
__device__ float g_ctx[MROWS*HH];     // [b*s, h]

// ---------------------------------------------------------------------------
// SGEMM: C[M,Nn] = A[M,K] @ B[K,Nn] (+bias). mode 0: plain write to C.
// mode 1: scatter epilogue into g_q/g_k/g_v with head layout, q scaled 0.125.
// BM=BN=128, BK=16, 256 threads, 8x8 per thread.
// ---------------------------------------------------------------------------
#define BM 128
#define BN 128
#define BK 16
#define TM 8
#define TN 8

__global__ __launch_bounds__(256) void sgemm_kernel(
    const float* __restrict__ A, const float* __restrict__ Bm,
    const float* __restrict__ bias, float* __restrict__ C,
    int M, int Nn, int Kk, int mode)
{
    __shared__ float As[BK][BM + 4];   // transposed A tile: As[k][row]
    __shared__ float Bs[BK][BN];       // Bs[k][col]

    int tid = threadIdx.x;
    int bx = blockIdx.x, by = blockIdx.y;
    int tx = tid & 15, ty = tid >> 4;
    int row0 = ty * TM, col0 = tx * TN;

    float acc[TM][TN];
    #pragma unroll
    for (int i = 0; i < TM; ++i)
        #pragma unroll
        for (int j = 0; j < TN; ++j) acc[i][j] = 0.f;

    const float* Ab = A + (size_t)by * BM * Kk;
    const float* Bb = Bm + (size_t)bx * BN;

    for (int k0 = 0; k0 < Kk; k0 += BK) {
        // Load A tile 128x16 (coalesced float4, transposed store)
        #pragma unroll
        for (int it = 0; it < 2; ++it) {
            int idx = tid + it * 256;
            int r  = idx >> 2;            // 0..127
            int c4 = (idx & 3) << 2;      // 0,4,8,12
            float4 v = *reinterpret_cast<const float4*>(Ab + (size_t)r * Kk + k0 + c4);
            As[c4 + 0][r] = v.x; As[c4 + 1][r] = v.y;
            As[c4 + 2][r] = v.z; As[c4 + 3][r] = v.w;
        }
        // Load B tile 16x128
        #pragma unroll
        for (int it = 0; it < 2; ++it) {
            int idx = tid + it * 256;
            int r  = idx >> 5;            // 0..15
            int c4 = (idx & 31) << 2;     // 0..124
            float4 v = *reinterpret_cast<const float4*>(Bb + (size_t)(k0 + r) * Nn + c4);
            *reinterpret_cast<float4*>(&Bs[r][c4]) = v;
        }
        __syncthreads();

        #pragma unroll
        for (int k = 0; k < BK; ++k) {
            float a[TM], b[TN];
            #pragma unroll
            for (int i = 0; i < TM; ++i) a[i] = As[k][row0 + i];
            #pragma unroll
            for (int j = 0; j < TN; ++j) b[j] = Bs[k][col0 + j];
            #pragma unroll
            for (int i = 0; i < TM; ++i)
                #pragma unroll
                for (int j = 0; j < TN; ++j)
                    acc[i][j] = fmaf(a[i], b[j], acc[i][j]);
        }
        __syncthreads();
    }

    int gr0 = by * BM + row0;
    int gc0 = bx * BN + col0;

    if (mode == 0) {
        #pragma unroll
        for (int i = 0; i < TM; ++i) {
            size_t base = (size_t)(gr0 + i) * Nn + gc0;
            #pragma unroll
            for (int j = 0; j < TN; ++j)
                C[base + j] = acc[i][j] + bias[gc0 + j];
        }
    } else {
        // qkv scatter: Nn = 3072. col -> (which, n, d); row -> (b, s)
        #pragma unroll
        for (int i = 0; i < TM; ++i) {
            int r  = gr0 + i;
            int b_ = r >> 11;           // /2048
            int s_ = r & 2047;
            #pragma unroll
            for (int j = 0; j < TN; ++j) {
                int col = gc0 + j;
                float v = acc[i][j] + bias[col];
                int which = col >> 10;   // 0=q,1=k,2=v
                int h = col & 1023;
                int n = h >> 6, d = h & 63;
                size_t dst = ((size_t)(b_ * NH + n) * SS + s_) * HD + d;
                if (which == 0)       g_q[dst] = v * 0.125f;   // 1/sqrt(64)
                else if (which == 1)  g_k[dst] = v;
                else                  g_v[dst] = v;
            }
        }
    }
}

// ---------------------------------------------------------------------------
// Causal flash attention fp32. One CTA per (q-block of 64 rows, b*n).
// 256 threads = 16x16; each thread: 4x4 micro-tiles of S and O.
// smem: Qs[d][row] (64x65), KPs (K as [d][key], then P as [key][row]) 64x65,
//       Vs[key][d] 64x64.  Total 49664 B dynamic.
// ---------------------------------------------------------------------------
#define ATTN_SMEM ((64*65 + 64*65 + 64*64) * 4)

__global__ __launch_bounds__(256) void attn_kernel() {
    extern __shared__ float sm[];
    float* Qs  = sm;                 // Qs[d*65 + row]
    float* KPs = sm + 64 * 65;       // K: [d*65+key] ; P: [key*65+row]
    float* Vs  = sm + 2 * 64 * 65;   // [key*64 + d]

    int qb = blockIdx.x;             // 0..31
    int bn = blockIdx.y;             // 0..31
    const float* Qp = g_q + (size_t)bn * SS * HD;
    const float* Kp = g_k + (size_t)bn * SS * HD;
    const float* Vp = g_v + (size_t)bn * SS * HD;

    int tid = threadIdx.x;
    int tx = tid & 15, ty = tid >> 4;
    int row0 = ty * 4, col0 = tx * 4;

    // Load Q tile (64x64), store transposed d-major
    #pragma unroll
    for (int it = 0; it < 4; ++it) {
        int idx = tid + it * 256;
        int r  = idx >> 4;
        int c4 = (idx & 15) << 2;
        float4 v = *reinterpret_cast<const float4*>(Qp + (size_t)(qb * 64 + r) * HD + c4);
        Qs[(c4 + 0) * 65 + r] = v.x; Qs[(c4 + 1) * 65 + r] = v.y;
        Qs[(c4 + 2) * 65 + r] = v.z; Qs[(c4 + 3) * 65 + r] = v.w;
    }

    float accO[4][4];
    float m_run[4], l_run[4];
    #pragma unroll
    for (int i = 0; i < 4; ++i) {
        m_run[i] = -1e30f; l_run[i] = 0.f;
        #pragma unroll
        for (int j = 0; j < 4; ++j) accO[i][j] = 0.f;
    }

    for (int j = 0; j <= qb; ++j) {
        __syncthreads();   // prior iteration done reading KPs(P) and Vs
        // Load K (transposed) and V (natural) 64x64 tiles
        #pragma unroll
        for (int it = 0; it < 4; ++it) {
            int idx = tid + it * 256;
            int r  = idx >> 4;
            int c4 = (idx & 15) << 2;
            float4 kv = *reinterpret_cast<const float4*>(Kp + (size_t)(j * 64 + r) * HD + c4);
            KPs[(c4 + 0) * 65 + r] = kv.x; KPs[(c4 + 1) * 65 + r] = kv.y;
            KPs[(c4 + 2) * 65 + r] = kv.z; KPs[(c4 + 3) * 65 + r] = kv.w;
            float4 vv = *reinterpret_cast<const float4*>(Vp + (size_t)(j * 64 + r) * HD + c4);
            *reinterpret_cast<float4*>(Vs + r * 64 + c4) = vv;
        }
        __syncthreads();

        // S = Q @ K^T  (Q pre-scaled by 1/8)
        float s[4][4];
        #pragma unroll
        for (int i = 0; i < 4; ++i)
            #pragma unroll
            for (int jj = 0; jj < 4; ++jj) s[i][jj] = 0.f;

        #pragma unroll 4
        for (int d = 0; d < 64; ++d) {
            float a[4], b[4];
            #pragma unroll
            for (int i = 0; i < 4; ++i)  a[i]  = Qs[d * 65 + row0 + i];
            #pragma unroll
            for (int jj = 0; jj < 4; ++jj) b[jj] = KPs[d * 65 + col0 + jj];
            #pragma unroll
            for (int i = 0; i < 4; ++i)
                #pragma unroll
                for (int jj = 0; jj < 4; ++jj)
                    s[i][jj] = fmaf(a[i], b[jj], s[i][jj]);
        }

        // Causal mask on diagonal block
        if (j == qb) {
            #pragma unroll
            for (int i = 0; i < 4; ++i)
                #pragma unroll
                for (int jj = 0; jj < 4; ++jj)
                    if (col0 + jj > row0 + i) s[i][jj] = -1e30f;
        }

        // Online softmax: row reductions across the 16 threads sharing ty
        #pragma unroll
        for (int i = 0; i < 4; ++i) {
            float mx = fmaxf(fmaxf(s[i][0], s[i][1]), fmaxf(s[i][2], s[i][3]));
            #pragma unroll
            for (int off = 8; off >= 1; off >>= 1)
                mx = fmaxf(mx, __shfl_xor_sync(0xffffffffu, mx, off));
            float mnew = fmaxf(m_run[i], mx);
            float corr = __expf(m_run[i] - mnew);
            float ls = 0.f;
            #pragma unroll
            for (int jj = 0; jj < 4; ++jj) {
                float p = __expf(s[i][jj] - mnew);
                s[i][jj] = p;
                ls += p;
            }
            #pragma unroll
            for (int off = 8; off >= 1; off >>= 1)
                ls += __shfl_xor_sync(0xffffffffu, ls, off);
            l_run[i] = l_run[i] * corr + ls;
            m_run[i] = mnew;
            #pragma unroll
            for (int jj = 0; jj < 4; ++jj) accO[i][jj] *= corr;
        }

        __syncthreads();   // everyone done reading KPs as K
        // Store P transposed into KPs: P[key][row]
        #pragma unroll
        for (int i = 0; i < 4; ++i)
            #pragma unroll
            for (int jj = 0; jj < 4; ++jj)
                KPs[(col0 + jj) * 65 + row0 + i] = s[i][jj];
        __syncthreads();

        // O += P @ V
        #pragma unroll 4
        for (int k = 0; k < 64; ++k) {
            float a[4], b[4];
            #pragma unroll
            for (int i = 0; i < 4; ++i)  a[i]  = KPs[k * 65 + row0 + i];
            #pragma unroll
            for (int jj = 0; jj < 4; ++jj) b[jj] = Vs[k * 64 + col0 + jj];
            #pragma unroll
            for (int i = 0; i < 4; ++i)
                #pragma unroll
                for (int jj = 0; jj < 4; ++jj)
                    accO[i][jj] = fmaf(a[i], b[jj], accO[i][jj]);
        }
    }

    // Finalize and write ctx in [b*s, h] layout
    int b_ = bn >> 4, n = bn & 15;
    #pragma unroll
    for (int i = 0; i < 4; ++i) {
        float inv = 1.0f / l_run[i];
        int s_ = qb * 64 + row0 + i;
        float* dst = g_ctx + ((size_t)b_ * SS + s_) * HH + n * HD + col0;
        #pragma unroll
        for (int jj = 0; jj < 4; ++jj)
            dst[jj] = accO[i][jj] * inv;
    }
}

// ---------------------------------------------------------------------------
extern "C" void kernel_launch(void* const* d_in, const int* in_sizes, int n_in,
                              void* d_out, int out_size) {
    const float* hs      = (const float*)d_in[0];
    // d_in[1] = ltor_mask (pure causal tril -> not needed)
    const float* w_qkv   = (const float*)d_in[2];
    const float* b_qkv   = (const float*)d_in[3];
    const float* w_dense = (const float*)d_in[4];
    const float* b_dense = (const float*)d_in[5];
    float* out = (float*)d_out;

    void* ctx_ptr = nullptr;
    cudaGetSymbolAddress(&ctx_ptr, g_ctx);

    cudaFuncSetAttribute(attn_kernel,
                         cudaFuncAttributeMaxDynamicSharedMemorySize, ATTN_SMEM);

    // 1) QKV projection with head-layout scatter (q pre-scaled)
    dim3 g1(QKV_N / BN, MROWS / BM);   // (24, 32)
    sgemm_kernel<<<g1, 256>>>(hs, w_qkv, b_qkv, nullptr, MROWS, QKV_N, HH, 1);

    // 2) Causal flash attention
    dim3 g2(SS / 64, BB * NH);          // (32, 32)
    attn_kernel<<<g2, 256, ATTN_SMEM>>>();

    // 3) Output projection
    dim3 g3(HH / BN, MROWS / BM);       // (8, 32)
    sgemm_kernel<<<g3, 256>>>((const float*)ctx_ptr, w_dense, b_dense, out,
                              MROWS, HH, HH, 0);
}

// round 3
// speedup vs baseline: 2.3952x; 2.3952x over previous
#include <cuda_runtime.h>
#include <cuda_bf16.h>
#include <cstdint>

// Problem constants: B=2, S=2048, H=1024, N=16, HN=64
#define BB 2
#define SS 2048
#define HH 1024
#define NH 16
#define HD 64
#define MROWS (BB*SS)          // 4096
#define QKV_N (3*HH)           // 3072

// Device scratch (allocation-free rule -> __device__ globals)
__device__ float g_q[BB*NH*SS*HD];    // [b,n,s,d], pre-scaled by 1/sqrt(64)
__device__ float g_k[BB*NH*SS*HD];
__device__ float g_v[BB*NH*SS*HD];
__device__ float g_ctx[MROWS*HH];     // [b*s, h]

// ---------------------------------------------------------------------------
// tf32 helpers
// ---------------------------------------------------------------------------
__device__ __forceinline__ unsigned f2tf(float f) {
    unsigned u;
    asm("cvt.rna.tf32.f32 %0, %1;" : "=r"(u) : "f"(f));
    return u;
}

__device__ __forceinline__ void mma_tf32(float* d, const unsigned* a, const unsigned* b) {
    asm volatile(
        "mma.sync.aligned.m16n8k8.row.col.f32.tf32.tf32.f32 "
        "{%0,%1,%2,%3}, {%4,%5,%6,%7}, {%8,%9}, {%0,%1,%2,%3};"
        : "+f"(d[0]), "+f"(d[1]), "+f"(d[2]), "+f"(d[3])
        : "r"(a[0]), "r"(a[1]), "r"(a[2]), "r"(a[3]), "r"(b[0]), "r"(b[1]));
}

// ---------------------------------------------------------------------------
// tf32 tensor-core GEMM: C[M,Nn] = A[M,K] @ B[K,Nn] + bias
// Block 128x128, BK=32, 256 threads (8 warps: 4m x 2n), warp tile 32x64.
// mode 0: plain write to C. mode 1: scatter into g_q/g_k/g_v (q scaled 0.125).
// ---------------------------------------------------------------------------
#define GBK 32
#define GPAD 132

__global__ __launch_bounds__(256) void gemm_tf32(
    const float* __restrict__ A, const float* __restrict__ Bm,
    const float* __restrict__ bias, float* __restrict__ C,
    int Nn, int Kk, int mode)
{
    __shared__ unsigned As[GBK][GPAD];   // As[k][m]
    __shared__ unsigned Bs[GBK][GPAD];   // Bs[k][n]

    int tid = threadIdx.x;
    int wid = tid >> 5, lane = tid & 31;
    int g = lane >> 2, t = lane & 3;
    int wm = wid & 3, wn = wid >> 2;     // 4 x 2 warp grid
    int bx = blockIdx.x, by = blockIdx.y;

    const float* Ab = A + (size_t)by * 128 * Kk;
    const float* Bb = Bm + (size_t)bx * 128;

    float acc[2][8][4];
    #pragma unroll
    for (int mi = 0; mi < 2; ++mi)
        #pragma unroll
        for (int ni = 0; ni < 8; ++ni)
            #pragma unroll
            for (int c = 0; c < 4; ++c) acc[mi][ni][c] = 0.f;

    for (int k0 = 0; k0 < Kk; k0 += GBK) {
        // A tile: 128 rows x 32 cols -> transposed store As[k][m]
        #pragma unroll
        for (int it = 0; it < 4; ++it) {
            int idx = tid + it * 256;
            int r = idx >> 3;                 // 0..127
            int c4 = (idx & 7) << 2;          // 0..28
            float4 v = *reinterpret_cast<const float4*>(Ab + (size_t)r * Kk + k0 + c4);
            As[c4 + 0][r] = f2tf(v.x); As[c4 + 1][r] = f2tf(v.y);
            As[c4 + 2][r] = f2tf(v.z); As[c4 + 3][r] = f2tf(v.w);
        }
        // B tile: 32 rows x 128 cols -> Bs[k][n]
        #pragma unroll
        for (int it = 0; it < 4; ++it) {
            int idx = tid + it * 256;
            int r = idx >> 5;                 // 0..31
            int c4 = (idx & 31) << 2;         // 0..124
            float4 v = *reinterpret_cast<const float4*>(Bb + (size_t)(k0 + r) * Nn + c4);
            Bs[r][c4 + 0] = f2tf(v.x); Bs[r][c4 + 1] = f2tf(v.y);
            Bs[r][c4 + 2] = f2tf(v.z); Bs[r][c4 + 3] = f2tf(v.w);
        }
        __syncthreads();

        #pragma unroll
        for (int ks = 0; ks < 4; ++ks) {
            int kk = ks * 8;
            unsigned a[2][4], b[8][2];
            #pragma unroll
            for (int mi = 0; mi < 2; ++mi) {
                int m = wm * 32 + mi * 16;
                a[mi][0] = As[kk + t][m + g];
                a[mi][1] = As[kk + t][m + g + 8];
                a[mi][2] = As[kk + t + 4][m + g];
                a[mi][3] = As[kk + t + 4][m + g + 8];
            }
            #pragma unroll
            for (int ni = 0; ni < 8; ++ni) {
                int n = wn * 64 + ni * 8;
                b[ni][0] = Bs[kk + t][n + g];
                b[ni][1] = Bs[kk + t + 4][n + g];
            }
            #pragma unroll
            for (int mi = 0; mi < 2; ++mi)
                #pragma unroll
                for (int ni = 0; ni < 8; ++ni)
                    mma_tf32(acc[mi][ni], a[mi], b[ni]);
        }
        __syncthreads();
    }

    // Epilogue
    #pragma unroll
    for (int mi = 0; mi < 2; ++mi) {
        int r0 = by * 128 + wm * 32 + mi * 16 + g;   // rows r0 (c0,c1) and r0+8 (c2,c3)
        #pragma unroll
        for (int ni = 0; ni < 8; ++ni) {
            int c0 = bx * 128 + wn * 64 + ni * 8 + t * 2;
            float v00 = acc[mi][ni][0] + bias[c0];
            float v01 = acc[mi][ni][1] + bias[c0 + 1];
            float v10 = acc[mi][ni][2] + bias[c0];
            float v11 = acc[mi][ni][3] + bias[c0 + 1];
            if (mode == 0) {
                C[(size_t)r0 * Nn + c0]           = v00;
                C[(size_t)r0 * Nn + c0 + 1]       = v01;
                C[(size_t)(r0 + 8) * Nn + c0]     = v10;
                C[(size_t)(r0 + 8) * Nn + c0 + 1] = v11;
            } else {
                #pragma unroll
                for (int e = 0; e < 4; ++e) {
                    int rr = r0 + (e >> 1) * 8;
                    int cc = c0 + (e & 1);
                    float v = (e == 0) ? v00 : (e == 1) ? v01 : (e == 2) ? v10 : v11;
                    int b_ = rr >> 11;
                    int s_ = rr & 2047;
                    int which = cc >> 10;
                    int h = cc & 1023;
                    int n = h >> 6, d = h & 63;
                    size_t dst = ((size_t)(b_ * NH + n) * SS + s_) * HD + d;
                    if (which == 0)       g_q[dst] = v * 0.125f;
                    else if (which == 1)  g_k[dst] = v;
                    else                  g_v[dst] = v;
                }
            }
        }
    }
}

// ---------------------------------------------------------------------------
// Causal flash attention, tf32 tensor cores.
// CTA: 128 threads (4 warps), 64 q-rows per CTA (16 per warp).
// smem (tf32 bits): Qs[64][68], KP[64][68] (K tile, then aliased as P tile),
//                   Vs[64][68]. 52224 B dynamic.
// ---------------------------------------------------------------------------
#define APAD 68
#define ATTN_SMEM (3 * 64 * APAD * 4)

__global__ __launch_bounds__(128) void attn_tf32() {
    extern __shared__ unsigned sm[];
    unsigned* Qs = sm;                   // [row][d]   stride 68
    unsigned* KP = sm + 64 * APAD;       // K: [key][d]; later P: [row][key]
    unsigned* Vs = sm + 2 * 64 * APAD;   // [key][d]

    int qb = blockIdx.x;                 // 0..31
    int bn = blockIdx.y;                 // 0..31
    const float* Qp = g_q + (size_t)bn * SS * HD;
    const float* Kp = g_k + (size_t)bn * SS * HD;
    const float* Vp = g_v + (size_t)bn * SS * HD;

    int tid = threadIdx.x;
    int wid = tid >> 5, lane = tid & 31;
    int g = lane >> 2, t = lane & 3;
    int row0 = wid * 16;                 // warp's q rows: row0..row0+15

    // Load Q tile (64x64) row-major
    #pragma unroll
    for (int it = 0; it < 8; ++it) {
        int idx = tid + it * 128;
        int r = idx >> 4;
        int c4 = (idx & 15) << 2;
        float4 v = *reinterpret_cast<const float4*>(Qp + (size_t)(qb * 64 + r) * HD + c4);
        Qs[r * APAD + c4 + 0] = f2tf(v.x); Qs[r * APAD + c4 + 1] = f2tf(v.y);
        Qs[r * APAD + c4 + 2] = f2tf(v.z); Qs[r * APAD + c4 + 3] = f2tf(v.w);
    }

    float accO[8][4];
    #pragma unroll
    for (int ni = 0; ni < 8; ++ni)
        #pragma unroll
        for (int c = 0; c < 4; ++c) accO[ni][c] = 0.f;
    float mr0 = -1e30f, mr1 = -1e30f, lr0 = 0.f, lr1 = 0.f;

    for (int j = 0; j <= qb; ++j) {
        __syncthreads();    // previous iteration done with KP(P) and Vs
        #pragma unroll
        for (int it = 0; it < 8; ++it) {
            int idx = tid + it * 128;
            int r = idx >> 4;
            int c4 = (idx & 15) << 2;
            float4 kv = *reinterpret_cast<const float4*>(Kp + (size_t)(j * 64 + r) * HD + c4);
            KP[r * APAD + c4 + 0] = f2tf(kv.x); KP[r * APAD + c4 + 1] = f2tf(kv.y);
            KP[r * APAD + c4 + 2] = f2tf(kv.z); KP[r * APAD + c4 + 3] = f2tf(kv.w);
            float4 vv = *reinterpret_cast<const float4*>(Vp + (size_t)(j * 64 + r) * HD + c4);
            Vs[r * APAD + c4 + 0] = f2tf(vv.x); Vs[r * APAD + c4 + 1] = f2tf(vv.y);
            Vs[r * APAD + c4 + 2] = f2tf(vv.z); Vs[r * APAD + c4 + 3] = f2tf(vv.w);
        }
        __syncthreads();

        // S = Q @ K^T : m16 x n64 x k64 per warp
        float s[8][4];
        #pragma unroll
        for (int ni = 0; ni < 8; ++ni)
            #pragma unroll
            for (int c = 0; c < 4; ++c) s[ni][c] = 0.f;

        #pragma unroll
        for (int ks = 0; ks < 8; ++ks) {
            int kk = ks * 8;
            unsigned a[4];
            a[0] = Qs[(row0 + g) * APAD + kk + t];
            a[1] = Qs[(row0 + g + 8) * APAD + kk + t];
            a[2] = Qs[(row0 + g) * APAD + kk + t + 4];
            a[3] = Qs[(row0 + g + 8) * APAD + kk + t + 4];
            #pragma unroll
            for (int ni = 0; ni < 8; ++ni) {
                unsigned b[2];
                b[0] = KP[(ni * 8 + g) * APAD + kk + t];
                b[1] = KP[(ni * 8 + g) * APAD + kk + t + 4];
                mma_tf32(s[ni], a, b);
            }
        }

        // Causal mask on diagonal block
        if (j == qb) {
            #pragma unroll
            for (int ni = 0; ni < 8; ++ni) {
                int c0 = ni * 8 + t * 2;
                int r0a = row0 + g, r1a = row0 + g + 8;
                if (c0     > r0a) s[ni][0] = -1e30f;
                if (c0 + 1 > r0a) s[ni][1] = -1e30f;
                if (c0     > r1a) s[ni][2] = -1e30f;
                if (c0 + 1 > r1a) s[ni][3] = -1e30f;
            }
        }

        // Online softmax: two rows per thread, values spread over quad (t lanes)
        float mx0 = -1e30f, mx1 = -1e30f;
        #pragma unroll
        for (int ni = 0; ni < 8; ++ni) {
            mx0 = fmaxf(mx0, fmaxf(s[ni][0], s[ni][1]));
            mx1 = fmaxf(mx1, fmaxf(s[ni][2], s[ni][3]));
        }
        mx0 = fmaxf(mx0, __shfl_xor_sync(0xffffffffu, mx0, 1));
        mx0 = fmaxf(mx0, __shfl_xor_sync(0xffffffffu, mx0, 2));
        mx1 = fmaxf(mx1, __shfl_xor_sync(0xffffffffu, mx1, 1));
        mx1 = fmaxf(mx1, __shfl_xor_sync(0xffffffffu, mx1, 2));

        float mn0 = fmaxf(mr0, mx0), mn1 = fmaxf(mr1, mx1);
        float corr0 = __expf(mr0 - mn0), corr1 = __expf(mr1 - mn1);
        float sum0 = 0.f, sum1 = 0.f;
        #pragma unroll
        for (int ni = 0; ni < 8; ++ni) {
            s[ni][0] = __expf(s[ni][0] - mn0);
            s[ni][1] = __expf(s[ni][1] - mn0);
            s[ni][2] = __expf(s[ni][2] - mn1);
            s[ni][3] = __expf(s[ni][3] - mn1);
            sum0 += s[ni][0] + s[ni][1];
            sum1 += s[ni][2] + s[ni][3];
        }
        sum0 += __shfl_xor_sync(0xffffffffu, sum0, 1);
        sum0 += __shfl_xor_sync(0xffffffffu, sum0, 2);
        sum1 += __shfl_xor_sync(0xffffffffu, sum1, 1);
        sum1 += __shfl_xor_sync(0xffffffffu, sum1, 2);
        lr0 = lr0 * corr0 + sum0;
        lr1 = lr1 * corr1 + sum1;
        mr0 = mn0; mr1 = mn1;
        #pragma unroll
        for (int ni = 0; ni < 8; ++ni) {
            accO[ni][0] *= corr0; accO[ni][1] *= corr0;
            accO[ni][2] *= corr1; accO[ni][3] *= corr1;
        }

        __syncthreads();    // all warps done reading KP as K
        // Write P into KP: [row][key], stride 68 (each warp owns its 16 rows)
        #pragma unroll
        for (int ni = 0; ni < 8; ++ni) {
            int c0 = ni * 8 + t * 2;
            KP[(row0 + g) * APAD + c0]         = f2tf(s[ni][0]);
            KP[(row0 + g) * APAD + c0 + 1]     = f2tf(s[ni][1]);
            KP[(row0 + g + 8) * APAD + c0]     = f2tf(s[ni][2]);
            KP[(row0 + g + 8) * APAD + c0 + 1] = f2tf(s[ni][3]);
        }
        __syncwarp();       // warp reads only its own rows

        // O += P @ V : k = key (64), n = d (64)
        #pragma unroll
        for (int ks = 0; ks < 8; ++ks) {
            int kk = ks * 8;
            unsigned a[4];
            a[0] = KP[(row0 + g) * APAD + kk + t];
            a[1] = KP[(row0 + g + 8) * APAD + kk + t];
            a[2] = KP[(row0 + g) * APAD + kk + t + 4];
            a[3] = KP[(row0 + g + 8) * APAD + kk + t + 4];
            #pragma unroll
            for (int ni = 0; ni < 8; ++ni) {
                unsigned b[2];
                b[0] = Vs[(kk + t) * APAD + ni * 8 + g];
                b[1] = Vs[(kk + t + 4) * APAD + ni * 8 + g];
                mma_tf32(accO[ni], a, b);
            }
        }
    }

    // Finalize: write ctx in [b*s, h] layout
    int b_ = bn >> 4, n = bn & 15;
    float inv0 = 1.0f / lr0, inv1 = 1.0f / lr1;
    int s0 = qb * 64 + row0 + g;
    int s1 = s0 + 8;
    #pragma unroll
    for (int ni = 0; ni < 8; ++ni) {
        int c0 = n * HD + ni * 8 + t * 2;
        g_ctx[((size_t)b_ * SS + s0) * HH + c0]     = accO[ni][0] * inv0;
        g_ctx[((size_t)b_ * SS + s0) * HH + c0 + 1] = accO[ni][1] * inv0;
        g_ctx[((size_t)b_ * SS + s1) * HH + c0]     = accO[ni][2] * inv1;
        g_ctx[((size_t)b_ * SS + s1) * HH + c0 + 1] = accO[ni][3] * inv1;
    }
}

// ---------------------------------------------------------------------------
extern "C" void kernel_launch(void* const* d_in, const int* in_sizes, int n_in,
                              void* d_out, int out_size) {
    const float* hs      = (const float*)d_in[0];
    // d_in[1] = ltor_mask (pure causal tril -> not needed)
    const float* w_qkv   = (const float*)d_in[2];
    const float* b_qkv   = (const float*)d_in[3];
    const float* w_dense = (const float*)d_in[4];
    const float* b_dense = (const float*)d_in[5];
    float* out = (float*)d_out;

    void* ctx_ptr = nullptr;
    cudaGetSymbolAddress(&ctx_ptr, g_ctx);

    cudaFuncSetAttribute(attn_tf32,
                         cudaFuncAttributeMaxDynamicSharedMemorySize, ATTN_SMEM);

    // 1) QKV projection with head-layout scatter (q pre-scaled)
    dim3 g1(QKV_N / 128, MROWS / 128);   // (24, 32)
    gemm_tf32<<<g1, 256>>>(hs, w_qkv, b_qkv, nullptr, QKV_N, HH, 1);

    // 2) Causal flash attention
    dim3 g2(SS / 64, BB * NH);           // (32, 32)
    attn_tf32<<<g2, 128, ATTN_SMEM>>>();

    // 3) Output projection
    dim3 g3(HH / 128, MROWS / 128);      // (8, 32)
    gemm_tf32<<<g3, 256>>>((const float*)ctx_ptr, w_dense, b_dense, out,
                           HH, HH, 0);
}

// round 4
// speedup vs baseline: 5.2305x; 2.1837x over previous
#include <cuda_runtime.h>
#include <cuda_fp16.h>
#include <cstdint>

// Problem constants: B=2, S=2048, H=1024, N=16, HN=64
#define BB 2
#define SS 2048
#define HH 1024
#define NH 16
#define HD 64
#define MROWS (BB*SS)          // 4096
#define QKV_N (3*HH)           // 3072

// Device scratch (allocation-free rule -> __device__ globals), fp16
__device__ __half g_q[BB*NH*SS*HD];    // [b,n,s,d], pre-scaled by 1/sqrt(64)
__device__ __half g_k[BB*NH*SS*HD];
__device__ __half g_v[BB*NH*SS*HD];
__device__ __half g_ctx[MROWS*HH];     // [b*s, h]

// ---------------------------------------------------------------------------
// mma / ldmatrix helpers
// ---------------------------------------------------------------------------
__device__ __forceinline__ void mma_f16(float* d, const unsigned* a, const unsigned* b) {
    asm volatile(
        "mma.sync.aligned.m16n8k16.row.col.f32.f16.f16.f32 "
        "{%0,%1,%2,%3}, {%4,%5,%6,%7}, {%8,%9}, {%0,%1,%2,%3};"
        : "+f"(d[0]), "+f"(d[1]), "+f"(d[2]), "+f"(d[3])
        : "r"(a[0]), "r"(a[1]), "r"(a[2]), "r"(a[3]), "r"(b[0]), "r"(b[1]));
}

__device__ __forceinline__ void ldsm4(unsigned& r0, unsigned& r1, unsigned& r2, unsigned& r3,
                                      const void* p) {
    unsigned addr = (unsigned)__cvta_generic_to_shared(p);
    asm volatile("ldmatrix.sync.aligned.m8n8.x4.shared.b16 {%0,%1,%2,%3}, [%4];"
                 : "=r"(r0), "=r"(r1), "=r"(r2), "=r"(r3) : "r"(addr));
}

__device__ __forceinline__ void ldsm4t(unsigned& r0, unsigned& r1, unsigned& r2, unsigned& r3,
                                       const void* p) {
    unsigned addr = (unsigned)__cvta_generic_to_shared(p);
    asm volatile("ldmatrix.sync.aligned.m8n8.x4.trans.shared.b16 {%0,%1,%2,%3}, [%4];"
                 : "=r"(r0), "=r"(r1), "=r"(r2), "=r"(r3) : "r"(addr));
}

// ---------------------------------------------------------------------------
// fp16 tensor-core GEMM: C[M,Nn] = A[M,K] @ B[K,Nn] + bias
// Block 128x128, BK=32, 256 threads (8 warps: 4m x 2n), warp tile 32x64.
// A in smem row-major [m][k] (LDA=40 halves), B in smem [k][n] (LDB=136),
// fragments via ldmatrix (A non-trans, B trans).
// mode 0: write float C. mode 1: scatter half into g_q/g_k/g_v (q * 0.125).
// ---------------------------------------------------------------------------
#define LDA 40
#define LDB 136

template<typename AT>
__global__ __launch_bounds__(256) void gemm_f16(
    const AT* __restrict__ A, const float* __restrict__ Bm,
    const float* __restrict__ bias, float* __restrict__ C,
    int Nn, int Kk, int mode)
{
    __shared__ __half As[128][LDA];
    __shared__ __half Bs[32][LDB];

    int tid = threadIdx.x;
    int wid = tid >> 5, lane = tid & 31;
    int g = lane >> 2, t = lane & 3;
    int wm = wid & 3, wn = wid >> 2;         // 4 x 2 warp grid
    int bx = blockIdx.x, by = blockIdx.y;

    const AT* Ab = A + (size_t)by * 128 * Kk;
    const float* Bb = Bm + (size_t)bx * 128;

    float acc[2][8][4];
    #pragma unroll
    for (int mi = 0; mi < 2; ++mi)
        #pragma unroll
        for (int ni = 0; ni < 8; ++ni)
            #pragma unroll
            for (int c = 0; c < 4; ++c) acc[mi][ni][c] = 0.f;

    // ldmatrix lane addressing (precomputed row/col offsets)
    int a_r = lane & 15, a_c8 = (lane >> 4) << 3;              // A non-trans x4
    int b_r = ((lane >> 3) & 1) * 8 + (lane & 7);              // B trans x4 (row within k16)
    int b_c8 = (lane >> 4) << 3;                               // col offset within n16

    for (int k0 = 0; k0 < Kk; k0 += 32) {
        // ---- load A tile 128x32 ----
        if constexpr (sizeof(AT) == 4) {
            #pragma unroll
            for (int it = 0; it < 4; ++it) {
                int idx = tid + it * 256;
                int r = idx >> 3, c4 = (idx & 7) << 2;
                float4 v = *reinterpret_cast<const float4*>((const float*)Ab + (size_t)r * Kk + k0 + c4);
                *reinterpret_cast<__half2*>(&As[r][c4])     = __floats2half2_rn(v.x, v.y);
                *reinterpret_cast<__half2*>(&As[r][c4 + 2]) = __floats2half2_rn(v.z, v.w);
            }
        } else {
            #pragma unroll
            for (int it = 0; it < 2; ++it) {
                int idx = tid + it * 256;
                int r = idx >> 2, c8 = (idx & 3) << 3;
                float4 v = *reinterpret_cast<const float4*>((const __half*)Ab + (size_t)r * Kk + k0 + c8);
                *reinterpret_cast<float4*>(&As[r][c8]) = v;
            }
        }
        // ---- load B tile 32x128 ----
        #pragma unroll
        for (int it = 0; it < 4; ++it) {
            int idx = tid + it * 256;
            int r = idx >> 5, c4 = (idx & 31) << 2;
            float4 v = *reinterpret_cast<const float4*>(Bb + (size_t)(k0 + r) * Nn + c4);
            *reinterpret_cast<__half2*>(&Bs[r][c4])     = __floats2half2_rn(v.x, v.y);
            *reinterpret_cast<__half2*>(&Bs[r][c4 + 2]) = __floats2half2_rn(v.z, v.w);
        }
        __syncthreads();

        #pragma unroll
        for (int ks = 0; ks < 2; ++ks) {
            int kk = ks * 16;
            unsigned a[2][4], b[8][2];
            #pragma unroll
            for (int mi = 0; mi < 2; ++mi)
                ldsm4(a[mi][0], a[mi][1], a[mi][2], a[mi][3],
                      &As[wm * 32 + mi * 16 + a_r][kk + a_c8]);
            #pragma unroll
            for (int p = 0; p < 4; ++p) {
                int n0 = wn * 64 + p * 16;
                unsigned r0, r1, r2, r3;
                ldsm4t(r0, r1, r2, r3, &Bs[kk + b_r][n0 + b_c8]);
                b[2 * p][0] = r0; b[2 * p][1] = r1;
                b[2 * p + 1][0] = r2; b[2 * p + 1][1] = r3;
            }
            #pragma unroll
            for (int mi = 0; mi < 2; ++mi)
                #pragma unroll
                for (int ni = 0; ni < 8; ++ni)
                    mma_f16(acc[mi][ni], a[mi], b[ni]);
        }
        __syncthreads();
    }

    // Epilogue
    #pragma unroll
    for (int mi = 0; mi < 2; ++mi) {
        int r0 = by * 128 + wm * 32 + mi * 16 + g;   // rows r0 (c0,c1), r0+8 (c2,c3)
        #pragma unroll
        for (int ni = 0; ni < 8; ++ni) {
            int c0 = bx * 128 + wn * 64 + ni * 8 + t * 2;
            float v00 = acc[mi][ni][0] + bias[c0];
            float v01 = acc[mi][ni][1] + bias[c0 + 1];
            float v10 = acc[mi][ni][2] + bias[c0];
            float v11 = acc[mi][ni][3] + bias[c0 + 1];
            if (mode == 0) {
                C[(size_t)r0 * Nn + c0]           = v00;
                C[(size_t)r0 * Nn + c0 + 1]       = v01;
                C[(size_t)(r0 + 8) * Nn + c0]     = v10;
                C[(size_t)(r0 + 8) * Nn + c0 + 1] = v11;
            } else {
                #pragma unroll
                for (int e = 0; e < 4; ++e) {
                    int rr = r0 + (e >> 1) * 8;
                    int cc = c0 + (e & 1);
                    float v = (e == 0) ? v00 : (e == 1) ? v01 : (e == 2) ? v10 : v11;
                    int b_ = rr >> 11;
                    int s_ = rr & 2047;
                    int which = cc >> 10;
                    int h = cc & 1023;
                    int n = h >> 6, d = h & 63;
                    size_t dst = ((size_t)(b_ * NH + n) * SS + s_) * HD + d;
                    if (which == 0)       g_q[dst] = __float2half(v * 0.125f);
                    else if (which == 1)  g_k[dst] = __float2half(v);
                    else                  g_v[dst] = __float2half(v);
                }
            }
        }
    }
}

// ---------------------------------------------------------------------------
// Causal flash attention, fp16 tensor cores.
// CTA: 128 threads (4 warps), 64 q-rows per CTA (16 per warp), 64-key tiles.
// smem halves, row stride 72: Qs[64][72], KP[64][72] (K tile then P tile),
// Vs[64][72]. 27.6 KB static.
// ---------------------------------------------------------------------------
#define ALD 72

__global__ __launch_bounds__(128) void attn_f16() {
    __shared__ __half Qs[64][ALD];   // [row][d]
    __shared__ __half KP[64][ALD];   // K: [key][d]; later P: [row][key]
    __shared__ __half Vs[64][ALD];   // [key][d]

    int qb = blockIdx.x;             // 0..31
    int bn = blockIdx.y;             // 0..31
    const __half* Qp = g_q + (size_t)bn * SS * HD;
    const __half* Kp = g_k + (size_t)bn * SS * HD;
    const __half* Vp = g_v + (size_t)bn * SS * HD;

    int tid = threadIdx.x;
    int wid = tid >> 5, lane = tid & 31;
    int g = lane >> 2, t = lane & 3;
    int row0 = wid * 16;

    // ldmatrix lane offsets
    int a_r = lane & 15, a_c8 = (lane >> 4) << 3;                 // non-trans x4
    int kb_r = ((lane >> 4) & 1) * 8 + (lane & 7);                // K non-trans x4: row in n16
    int kb_c8 = ((lane >> 3) & 1) * 8;                            // col in k16
    int vb_r = ((lane >> 3) & 1) * 8 + (lane & 7);                // V trans x4: row in k16
    int vb_c8 = (lane >> 4) << 3;                                 // col in n16

    // Load Q tile (64x64 halves)
    #pragma unroll
    for (int it = 0; it < 4; ++it) {
        int idx = tid + it * 128;
        int r = idx >> 3, c8 = (idx & 7) << 3;
        float4 v = *reinterpret_cast<const float4*>(Qp + (size_t)(qb * 64 + r) * HD + c8);
        *reinterpret_cast<float4*>(&Qs[r][c8]) = v;
    }

    float accO[8][4];
    #pragma unroll
    for (int ni = 0; ni < 8; ++ni)
        #pragma unroll
        for (int c = 0; c < 4; ++c) accO[ni][c] = 0.f;
    float mr0 = -1e30f, mr1 = -1e30f, lr0 = 0.f, lr1 = 0.f;

    for (int j = 0; j <= qb; ++j) {
        __syncthreads();
        #pragma unroll
        for (int it = 0; it < 4; ++it) {
            int idx = tid + it * 128;
            int r = idx >> 3, c8 = (idx & 7) << 3;
            float4 kv = *reinterpret_cast<const float4*>(Kp + (size_t)(j * 64 + r) * HD + c8);
            *reinterpret_cast<float4*>(&KP[r][c8]) = kv;
            float4 vv = *reinterpret_cast<const float4*>(Vp + (size_t)(j * 64 + r) * HD + c8);
            *reinterpret_cast<float4*>(&Vs[r][c8]) = vv;
        }
        __syncthreads();

        // S = Q @ K^T : m16 x n64 x k64 per warp
        float s[8][4];
        #pragma unroll
        for (int ni = 0; ni < 8; ++ni)
            #pragma unroll
            for (int c = 0; c < 4; ++c) s[ni][c] = 0.f;

        #pragma unroll
        for (int ks = 0; ks < 4; ++ks) {
            int kk = ks * 16;
            unsigned a[4];
            ldsm4(a[0], a[1], a[2], a[3], &Qs[row0 + a_r][kk + a_c8]);
            #pragma unroll
            for (int p = 0; p < 4; ++p) {
                int n0 = p * 16;
                unsigned r0, r1, r2, r3;
                ldsm4(r0, r1, r2, r3, &KP[n0 + kb_r][kk + kb_c8]);
                unsigned b0[2] = {r0, r1}, b1[2] = {r2, r3};
                mma_f16(s[2 * p], a, b0);
                mma_f16(s[2 * p + 1], a, b1);
            }
        }

        // Causal mask on diagonal block
        if (j == qb) {
            #pragma unroll
            for (int ni = 0; ni < 8; ++ni) {
                int c0 = ni * 8 + t * 2;
                int r0a = row0 + g, r1a = r0a + 8;
                if (c0     > r0a) s[ni][0] = -1e30f;
                if (c0 + 1 > r0a) s[ni][1] = -1e30f;
                if (c0     > r1a) s[ni][2] = -1e30f;
                if (c0 + 1 > r1a) s[ni][3] = -1e30f;
            }
        }

        // Online softmax (fp32), rows spread over quad lanes
        float mx0 = -1e30f, mx1 = -1e30f;
        #pragma unroll
        for (int ni = 0; ni < 8; ++ni) {
            mx0 = fmaxf(mx0, fmaxf(s[ni][0], s[ni][1]));
            mx1 = fmaxf(mx1, fmaxf(s[ni][2], s[ni][3]));
        }
        mx0 = fmaxf(mx0, __shfl_xor_sync(0xffffffffu, mx0, 1));
        mx0 = fmaxf(mx0, __shfl_xor_sync(0xffffffffu, mx0, 2));
        mx1 = fmaxf(mx1, __shfl_xor_sync(0xffffffffu, mx1, 1));
        mx1 = fmaxf(mx1, __shfl_xor_sync(0xffffffffu, mx1, 2));

        float mn0 = fmaxf(mr0, mx0), mn1 = fmaxf(mr1, mx1);
        float corr0 = __expf(mr0 - mn0), corr1 = __expf(mr1 - mn1);
        float sum0 = 0.f, sum1 = 0.f;
        #pragma unroll
        for (int ni = 0; ni < 8; ++ni) {
            s[ni][0] = __expf(s[ni][0] - mn0);
            s[ni][1] = __expf(s[ni][1] - mn0);
            s[ni][2] = __expf(s[ni][2] - mn1);
            s[ni][3] = __expf(s[ni][3] - mn1);
            sum0 += s[ni][0] + s[ni][1];
            sum1 += s[ni][2] + s[ni][3];
        }
        sum0 += __shfl_xor_sync(0xffffffffu, sum0, 1);
        sum0 += __shfl_xor_sync(0xffffffffu, sum0, 2);
        sum1 += __shfl_xor_sync(0xffffffffu, sum1, 1);
        sum1 += __shfl_xor_sync(0xffffffffu, sum1, 2);
        lr0 = lr0 * corr0 + sum0;
        lr1 = lr1 * corr1 + sum1;
        mr0 = mn0; mr1 = mn1;
        #pragma unroll
        for (int ni = 0; ni < 8; ++ni) {
            accO[ni][0] *= corr0; accO[ni][1] *= corr0;
            accO[ni][2] *= corr1; accO[ni][3] *= corr1;
        }

        __syncthreads();   // all warps done reading KP as K
        // Write P (half2) into KP: [row][key]; each warp owns its 16 rows
        #pragma unroll
        for (int ni = 0; ni < 8; ++ni) {
            int c0 = ni * 8 + t * 2;
            *reinterpret_cast<__half2*>(&KP[row0 + g][c0])     = __floats2half2_rn(s[ni][0], s[ni][1]);
            *reinterpret_cast<__half2*>(&KP[row0 + g + 8][c0]) = __floats2half2_rn(s[ni][2], s[ni][3]);
        }
        __syncwarp();

        // O += P @ V : k = key (64), n = d (64)
        #pragma unroll
        for (int ks = 0; ks < 4; ++ks) {
            int kk = ks * 16;
            unsigned a[4];
            ldsm4(a[0], a[1], a[2], a[3], &KP[row0 + a_r][kk + a_c8]);
            #pragma unroll
            for (int p = 0; p < 4; ++p) {
                int n0 = p * 16;
                unsigned r0, r1, r2, r3;
                ldsm4t(r0, r1, r2, r3, &Vs[kk + vb_r][n0 + vb_c8]);
                unsigned b0[2] = {r0, r1}, b1[2] = {r2, r3};
                mma_f16(accO[2 * p], a, b0);
                mma_f16(accO[2 * p + 1], a, b1);
            }
        }
    }

    // Finalize: write ctx (half) in [b*s, h] layout
    int b_ = bn >> 4, n = bn & 15;
    float inv0 = 1.0f / lr0, inv1 = 1.0f / lr1;
    int s0 = qb * 64 + row0 + g;
    int s1 = s0 + 8;
    #pragma unroll
    for (int ni = 0; ni < 8; ++ni) {
        int c0 = n * HD + ni * 8 + t * 2;
        *reinterpret_cast<__half2*>(&g_ctx[((size_t)b_ * SS + s0) * HH + c0]) =
            __floats2half2_rn(accO[ni][0] * inv0, accO[ni][1] * inv0);
        *reinterpret_cast<__half2*>(&g_ctx[((size_t)b_ * SS + s1) * HH + c0]) =
            __floats2half2_rn(accO[ni][2] * inv1, accO[ni][3] * inv1);
    }
}

// ---------------------------------------------------------------------------
extern "C" void kernel_launch(void* const* d_in, const int* in_sizes, int n_in,
                              void* d_out, int out_size) {
    const float* hs      = (const float*)d_in[0];
    // d_in[1] = ltor_mask (pure causal tril -> not needed)
    const float* w_qkv   = (const float*)d_in[2];
    const float* b_qkv   = (const float*)d_in[3];
    const float* w_dense = (const float*)d_in[4];
    const float* b_dense = (const float*)d_in[5];
    float* out = (float*)d_out;

    void* ctx_ptr = nullptr;
    cudaGetSymbolAddress(&ctx_ptr, g_ctx);

    // 1) QKV projection with head-layout scatter (q pre-scaled), fp32 A
    dim3 g1(QKV_N / 128, MROWS / 128);   // (24, 32)
    gemm_f16<float><<<g1, 256>>>(hs, w_qkv, b_qkv, nullptr, QKV_N, HH, 1);

    // 2) Causal flash attention
    dim3 g2(SS / 64, BB * NH);           // (32, 32)
    attn_f16<<<g2, 128>>>();

    // 3) Output projection, fp16 A (ctx)
    dim3 g3(HH / 128, MROWS / 128);      // (8, 32)
    gemm_f16<__half><<<g3, 256>>>((const __half*)ctx_ptr, w_dense, b_dense, out,
                                  HH, HH, 0);
}

// round 5
// speedup vs baseline: 6.4231x; 1.2280x over previous
#include <cuda_runtime.h>
#include <cuda_fp16.h>
#include <cstdint>

// Problem constants: B=2, S=2048, H=1024, N=16, HN=64
#define BB 2
#define SS 2048
#define HH 1024
#define NH 16
#define HD 64
#define MROWS (BB*SS)          // 4096
#define QKV_N (3*HH)           // 3072

// Device scratch (allocation-free rule -> __device__ globals), fp16
__device__ __half g_q[BB*NH*SS*HD];
__device__ __half g_k[BB*NH*SS*HD];
__device__ __half g_v[BB*NH*SS*HD];
__device__ __half g_ctx[MROWS*HH];
__device__ __half g_hs[MROWS*HH];      // fp16 hidden_states
__device__ __half g_wqkv[HH*QKV_N];    // fp16 w_qkv
__device__ __half g_wd[HH*HH];         // fp16 w_dense

// ---------------------------------------------------------------------------
// helpers
// ---------------------------------------------------------------------------
__device__ __forceinline__ void mma_f16(float* d, const unsigned* a, const unsigned* b) {
    asm volatile(
        "mma.sync.aligned.m16n8k16.row.col.f32.f16.f16.f32 "
        "{%0,%1,%2,%3}, {%4,%5,%6,%7}, {%8,%9}, {%0,%1,%2,%3};"
        : "+f"(d[0]), "+f"(d[1]), "+f"(d[2]), "+f"(d[3])
        : "r"(a[0]), "r"(a[1]), "r"(a[2]), "r"(a[3]), "r"(b[0]), "r"(b[1]));
}

__device__ __forceinline__ void ldsm4(unsigned& r0, unsigned& r1, unsigned& r2, unsigned& r3,
                                      const void* p) {
    unsigned addr = (unsigned)__cvta_generic_to_shared(p);
    asm volatile("ldmatrix.sync.aligned.m8n8.x4.shared.b16 {%0,%1,%2,%3}, [%4];"
                 : "=r"(r0), "=r"(r1), "=r"(r2), "=r"(r3) : "r"(addr));
}

__device__ __forceinline__ void ldsm4t(unsigned& r0, unsigned& r1, unsigned& r2, unsigned& r3,
                                       const void* p) {
    unsigned addr = (unsigned)__cvta_generic_to_shared(p);
    asm volatile("ldmatrix.sync.aligned.m8n8.x4.trans.shared.b16 {%0,%1,%2,%3}, [%4];"
                 : "=r"(r0), "=r"(r1), "=r"(r2), "=r"(r3) : "r"(addr));
}

__device__ __forceinline__ void cpa16(void* dst, const void* src) {
    unsigned d = (unsigned)__cvta_generic_to_shared(dst);
    asm volatile("cp.async.cg.shared.global [%0], [%1], 16;" :: "r"(d), "l"(src));
}
__device__ __forceinline__ void cp_commit() {
    asm volatile("cp.async.commit_group;");
}

// ---------------------------------------------------------------------------
// fp32 -> fp16 conversion (one-time)
// ---------------------------------------------------------------------------
__global__ __launch_bounds__(256) void f2h_kernel(const float* __restrict__ in,
                                                  __half* __restrict__ out, int n) {
    int i = (blockIdx.x * 256 + threadIdx.x) * 8;
    if (i >= n) return;
    float4 a = *reinterpret_cast<const float4*>(in + i);
    float4 b = *reinterpret_cast<const float4*>(in + i + 4);
    __half2 h[4] = { __floats2half2_rn(a.x, a.y), __floats2half2_rn(a.z, a.w),
                     __floats2half2_rn(b.x, b.y), __floats2half2_rn(b.z, b.w) };
    *reinterpret_cast<float4*>(out + i) = *reinterpret_cast<float4*>(h);
}

// ---------------------------------------------------------------------------
// fp16 GEMM, cp.async double-buffered: C[M,Nn] = A[M,K] @ B[K,Nn] + bias
// Block 128x128, BK=64, 2 stages, 256 threads (8 warps: 4m x 2n).
// A smem row-major [m][k] LDA=72, B smem [k][n] LDB=136 (both padded).
// mode 0: write float C. mode 1: scatter half into g_q/g_k/g_v (q * 0.125).
// ---------------------------------------------------------------------------
#define GBK 64
#define GLDA 72
#define GLDB 136
#define GA_ST (128 * GLDA)                 // halves per A stage
#define GB_ST (GBK * GLDB)                 // halves per B stage
#define GEMM_SMEM ((2 * GA_ST + 2 * GB_ST) * 2)   // 71680 B

__global__ __launch_bounds__(256) void gemm_f16(
    const __half* __restrict__ A, const __half* __restrict__ Bm,
    const float* __restrict__ bias, float* __restrict__ C,
    int Nn, int Kk, int mode)
{
    extern __shared__ __half gsm[];
    __half* As = gsm;                      // [2][128][GLDA]
    __half* Bs = gsm + 2 * GA_ST;          // [2][GBK][GLDB]

    int tid = threadIdx.x;
    int wid = tid >> 5, lane = tid & 31;
    int g = lane >> 2, t = lane & 3;
    int wm = wid & 3, wn = wid >> 2;       // 4 x 2 warp grid
    int bx = blockIdx.x, by = blockIdx.y;

    const __half* Ab = A + (size_t)by * 128 * Kk;
    const __half* Bb = Bm + (size_t)bx * 128;

    float acc[2][8][4];
    #pragma unroll
    for (int mi = 0; mi < 2; ++mi)
        #pragma unroll
        for (int ni = 0; ni < 8; ++ni)
            #pragma unroll
            for (int c = 0; c < 4; ++c) acc[mi][ni][c] = 0.f;

    // ldmatrix lane offsets
    int a_r = lane & 15, a_c8 = (lane >> 4) << 3;     // A non-trans x4
    int b_r = ((lane >> 3) & 1) * 8 + (lane & 7);     // B trans x4
    int b_c8 = (lane >> 4) << 3;

    // per-thread cp.async coordinates
    int ar[4], ac[4], br_[4], bc[4];
    #pragma unroll
    for (int it = 0; it < 4; ++it) {
        int idx = tid + it * 256;
        ar[it] = idx >> 3;  ac[it] = (idx & 7) << 3;      // A: 128 rows x 8 chunks
        br_[it] = idx >> 4; bc[it] = (idx & 15) << 3;     // B: 64 rows x 16 chunks
    }

    int nk = Kk / GBK;
    // prefetch stage 0
    #pragma unroll
    for (int it = 0; it < 4; ++it) {
        cpa16(&As[ar[it] * GLDA + ac[it]], Ab + (size_t)ar[it] * Kk + ac[it]);
        cpa16(&Bs[br_[it] * GLDB + bc[it]], Bb + (size_t)br_[it] * Nn + bc[it]);
    }
    cp_commit();

    for (int kt = 0; kt < nk; ++kt) {
        int st = kt & 1;
        if (kt + 1 < nk) {
            int k0 = (kt + 1) * GBK;
            __half* Ad = As + (st ^ 1) * GA_ST;
            __half* Bd = Bs + (st ^ 1) * GB_ST;
            #pragma unroll
            for (int it = 0; it < 4; ++it) {
                cpa16(&Ad[ar[it] * GLDA + ac[it]], Ab + (size_t)ar[it] * Kk + k0 + ac[it]);
                cpa16(&Bd[br_[it] * GLDB + bc[it]], Bb + (size_t)(k0 + br_[it]) * Nn + bc[it]);
            }
            cp_commit();
            asm volatile("cp.async.wait_group 1;");
        } else {
            asm volatile("cp.async.wait_group 0;");
        }
        __syncthreads();

        const __half* Ac = As + st * GA_ST;
        const __half* Bc = Bs + st * GB_ST;
        #pragma unroll
        for (int ks = 0; ks < 4; ++ks) {
            int kk = ks * 16;
            unsigned a[2][4], b[8][2];
            #pragma unroll
            for (int mi = 0; mi < 2; ++mi)
                ldsm4(a[mi][0], a[mi][1], a[mi][2], a[mi][3],
                      &Ac[(wm * 32 + mi * 16 + a_r) * GLDA + kk + a_c8]);
            #pragma unroll
            for (int p = 0; p < 4; ++p) {
                unsigned r0, r1, r2, r3;
                ldsm4t(r0, r1, r2, r3, &Bc[(kk + b_r) * GLDB + wn * 64 + p * 16 + b_c8]);
                b[2 * p][0] = r0; b[2 * p][1] = r1;
                b[2 * p + 1][0] = r2; b[2 * p + 1][1] = r3;
            }
            #pragma unroll
            for (int mi = 0; mi < 2; ++mi)
                #pragma unroll
                for (int ni = 0; ni < 8; ++ni)
                    mma_f16(acc[mi][ni], a[mi], b[ni]);
        }
        __syncthreads();
    }

    // Epilogue
    #pragma unroll
    for (int mi = 0; mi < 2; ++mi) {
        int r0 = by * 128 + wm * 32 + mi * 16 + g;
        #pragma unroll
        for (int ni = 0; ni < 8; ++ni) {
            int c0 = bx * 128 + wn * 64 + ni * 8 + t * 2;
            float v00 = acc[mi][ni][0] + bias[c0];
            float v01 = acc[mi][ni][1] + bias[c0 + 1];
            float v10 = acc[mi][ni][2] + bias[c0];
            float v11 = acc[mi][ni][3] + bias[c0 + 1];
            if (mode == 0) {
                C[(size_t)r0 * Nn + c0]           = v00;
                C[(size_t)r0 * Nn + c0 + 1]       = v01;
                C[(size_t)(r0 + 8) * Nn + c0]     = v10;
                C[(size_t)(r0 + 8) * Nn + c0 + 1] = v11;
            } else {
                #pragma unroll
                for (int e = 0; e < 4; ++e) {
                    int rr = r0 + (e >> 1) * 8;
                    int cc = c0 + (e & 1);
                    float v = (e == 0) ? v00 : (e == 1) ? v01 : (e == 2) ? v10 : v11;
                    int b_ = rr >> 11, s_ = rr & 2047;
                    int which = cc >> 10, h = cc & 1023;
                    int n = h >> 6, d = h & 63;
                    size_t dst = ((size_t)(b_ * NH + n) * SS + s_) * HD + d;
                    if (which == 0)       g_q[dst] = __float2half(v * 0.125f);
                    else if (which == 1)  g_k[dst] = __float2half(v);
                    else                  g_v[dst] = __float2half(v);
                }
            }
        }
    }
}

// ---------------------------------------------------------------------------
// Causal flash attention, fp16 tensor cores, cp.async double-buffered K/V.
// CTA: 128 threads (4 warps), 64 q-rows, 64-key tiles.
// smem: Qs[64][72], Ks[2][64][72], Vs[2][64][72], Ps[64][72] = 55296 B dyn.
// ---------------------------------------------------------------------------
#define ALD 72
#define AT_ST (64 * ALD)
#define ATTN_SMEM (6 * AT_ST * 2)

__global__ __launch_bounds__(128) void attn_f16() {
    extern __shared__ __half asm_[];
    __half* Qs = asm_;                     // [64][ALD]
    __half* Ks = asm_ + AT_ST;             // [2][64][ALD]
    __half* Vs = asm_ + 3 * AT_ST;         // [2][64][ALD]
    __half* Ps = asm_ + 5 * AT_ST;         // [64][ALD]

    int qb = blockIdx.x;                   // 0..31
    int bn = blockIdx.y;                   // 0..31
    const __half* Qp = g_q + (size_t)bn * SS * HD;
    const __half* Kp = g_k + (size_t)bn * SS * HD;
    const __half* Vp = g_v + (size_t)bn * SS * HD;

    int tid = threadIdx.x;
    int wid = tid >> 5, lane = tid & 31;
    int g = lane >> 2, t = lane & 3;
    int row0 = wid * 16;

    // ldmatrix lane offsets
    int a_r = lane & 15, a_c8 = (lane >> 4) << 3;
    int kb_r = ((lane >> 4) & 1) * 8 + (lane & 7);
    int kb_c8 = ((lane >> 3) & 1) * 8;
    int vb_r = ((lane >> 3) & 1) * 8 + (lane & 7);
    int vb_c8 = (lane >> 4) << 3;

    // cp.async coords: 64 rows x 8 chunks = 512 per tensor, 4 per thread each
    int cr[4], cc_[4];
    #pragma unroll
    for (int it = 0; it < 4; ++it) {
        int idx = tid + it * 128;
        cr[it] = idx >> 3; cc_[it] = (idx & 7) << 3;
    }

    // prefetch tile 0 (K+V) into stage 0
    #pragma unroll
    for (int it = 0; it < 4; ++it) {
        cpa16(&Ks[cr[it] * ALD + cc_[it]], Kp + (size_t)cr[it] * HD + cc_[it]);
        cpa16(&Vs[cr[it] * ALD + cc_[it]], Vp + (size_t)cr[it] * HD + cc_[it]);
    }
    cp_commit();

    // Q tile (plain loads, overlapped with prefetch)
    #pragma unroll
    for (int it = 0; it < 4; ++it) {
        float4 v = *reinterpret_cast<const float4*>(Qp + (size_t)(qb * 64 + cr[it]) * HD + cc_[it]);
        *reinterpret_cast<float4*>(&Qs[cr[it] * ALD + cc_[it]]) = v;
    }

    float accO[8][4];
    #pragma unroll
    for (int ni = 0; ni < 8; ++ni)
        #pragma unroll
        for (int c = 0; c < 4; ++c) accO[ni][c] = 0.f;
    float mr0 = -1e30f, mr1 = -1e30f, lr0 = 0.f, lr1 = 0.f;

    for (int j = 0; j <= qb; ++j) {
        int st = j & 1;
        if (j < qb) {
            const __half* Kn = Kp + (size_t)(j + 1) * 64 * HD;
            const __half* Vn = Vp + (size_t)(j + 1) * 64 * HD;
            __half* Kd = Ks + (st ^ 1) * AT_ST;
            __half* Vd = Vs + (st ^ 1) * AT_ST;
            #pragma unroll
            for (int it = 0; it < 4; ++it) {
                cpa16(&Kd[cr[it] * ALD + cc_[it]], Kn + (size_t)cr[it] * HD + cc_[it]);
                cpa16(&Vd[cr[it] * ALD + cc_[it]], Vn + (size_t)cr[it] * HD + cc_[it]);
            }
            cp_commit();
            asm volatile("cp.async.wait_group 1;");
        } else {
            asm volatile("cp.async.wait_group 0;");
        }
        __syncthreads();

        const __half* Kc = Ks + st * AT_ST;
        const __half* Vc = Vs + st * AT_ST;

        // S = Q @ K^T
        float s[8][4];
        #pragma unroll
        for (int ni = 0; ni < 8; ++ni)
            #pragma unroll
            for (int c = 0; c < 4; ++c) s[ni][c] = 0.f;

        #pragma unroll
        for (int ks = 0; ks < 4; ++ks) {
            int kk = ks * 16;
            unsigned a[4];
            ldsm4(a[0], a[1], a[2], a[3], &Qs[(row0 + a_r) * ALD + kk + a_c8]);
            #pragma unroll
            for (int p = 0; p < 4; ++p) {
                unsigned r0, r1, r2, r3;
                ldsm4(r0, r1, r2, r3, &Kc[(p * 16 + kb_r) * ALD + kk + kb_c8]);
                unsigned b0[2] = {r0, r1}, b1[2] = {r2, r3};
                mma_f16(s[2 * p], a, b0);
                mma_f16(s[2 * p + 1], a, b1);
            }
        }

        // causal mask on diagonal block
        if (j == qb) {
            #pragma unroll
            for (int ni = 0; ni < 8; ++ni) {
                int c0 = ni * 8 + t * 2;
                int r0a = row0 + g, r1a = r0a + 8;
                if (c0     > r0a) s[ni][0] = -1e30f;
                if (c0 + 1 > r0a) s[ni][1] = -1e30f;
                if (c0     > r1a) s[ni][2] = -1e30f;
                if (c0 + 1 > r1a) s[ni][3] = -1e30f;
            }
        }

        // online softmax
        float mx0 = -1e30f, mx1 = -1e30f;
        #pragma unroll
        for (int ni = 0; ni < 8; ++ni) {
            mx0 = fmaxf(mx0, fmaxf(s[ni][0], s[ni][1]));
            mx1 = fmaxf(mx1, fmaxf(s[ni][2], s[ni][3]));
        }
        mx0 = fmaxf(mx0, __shfl_xor_sync(0xffffffffu, mx0, 1));
        mx0 = fmaxf(mx0, __shfl_xor_sync(0xffffffffu, mx0, 2));
        mx1 = fmaxf(mx1, __shfl_xor_sync(0xffffffffu, mx1, 1));
        mx1 = fmaxf(mx1, __shfl_xor_sync(0xffffffffu, mx1, 2));

        float mn0 = fmaxf(mr0, mx0), mn1 = fmaxf(mr1, mx1);
        float corr0 = __expf(mr0 - mn0), corr1 = __expf(mr1 - mn1);
        float sum0 = 0.f, sum1 = 0.f;
        #pragma unroll
        for (int ni = 0; ni < 8; ++ni) {
            s[ni][0] = __expf(s[ni][0] - mn0);
            s[ni][1] = __expf(s[ni][1] - mn0);
            s[ni][2] = __expf(s[ni][2] - mn1);
            s[ni][3] = __expf(s[ni][3] - mn1);
            sum0 += s[ni][0] + s[ni][1];
            sum1 += s[ni][2] + s[ni][3];
        }
        sum0 += __shfl_xor_sync(0xffffffffu, sum0, 1);
        sum0 += __shfl_xor_sync(0xffffffffu, sum0, 2);
        sum1 += __shfl_xor_sync(0xffffffffu, sum1, 1);
        sum1 += __shfl_xor_sync(0xffffffffu, sum1, 2);
        lr0 = lr0 * corr0 + sum0;
        lr1 = lr1 * corr1 + sum1;
        mr0 = mn0; mr1 = mn1;
        #pragma unroll
        for (int ni = 0; ni < 8; ++ni) {
            accO[ni][0] *= corr0; accO[ni][1] *= corr0;
            accO[ni][2] *= corr1; accO[ni][3] *= corr1;
        }

        // P write: warp-private rows -> only __syncwarp needed
        #pragma unroll
        for (int ni = 0; ni < 8; ++ni) {
            int c0 = ni * 8 + t * 2;
            *reinterpret_cast<__half2*>(&Ps[(row0 + g) * ALD + c0])     = __floats2half2_rn(s[ni][0], s[ni][1]);
            *reinterpret_cast<__half2*>(&Ps[(row0 + g + 8) * ALD + c0]) = __floats2half2_rn(s[ni][2], s[ni][3]);
        }
        __syncwarp();

        // O += P @ V
        #pragma unroll
        for (int ks = 0; ks < 4; ++ks) {
            int kk = ks * 16;
            unsigned a[4];
            ldsm4(a[0], a[1], a[2], a[3], &Ps[(row0 + a_r) * ALD + kk + a_c8]);
            #pragma unroll
            for (int p = 0; p < 4; ++p) {
                unsigned r0, r1, r2, r3;
                ldsm4t(r0, r1, r2, r3, &Vc[(kk + vb_r) * ALD + p * 16 + vb_c8]);
                unsigned b0[2] = {r0, r1}, b1[2] = {r2, r3};
                mma_f16(accO[2 * p], a, b0);
                mma_f16(accO[2 * p + 1], a, b1);
            }
        }
        __syncthreads();   // all warps done with stage st before it's overwritten
    }

    // Finalize: write ctx (half) in [b*s, h] layout
    int b_ = bn >> 4, n = bn & 15;
    float inv0 = 1.0f / lr0, inv1 = 1.0f / lr1;
    int s0 = qb * 64 + row0 + g;
    int s1 = s0 + 8;
    #pragma unroll
    for (int ni = 0; ni < 8; ++ni) {
        int c0 = n * HD + ni * 8 + t * 2;
        *reinterpret_cast<__half2*>(&g_ctx[((size_t)b_ * SS + s0) * HH + c0]) =
            __floats2half2_rn(accO[ni][0] * inv0, accO[ni][1] * inv0);
        *reinterpret_cast<__half2*>(&g_ctx[((size_t)b_ * SS + s1) * HH + c0]) =
            __floats2half2_rn(accO[ni][2] * inv1, accO[ni][3] * inv1);
    }
}

// ---------------------------------------------------------------------------
extern "C" void kernel_launch(void* const* d_in, const int* in_sizes, int n_in,
                              void* d_out, int out_size) {
    const float* hs      = (const float*)d_in[0];
    const float* w_qkv   = (const float*)d_in[2];
    const float* b_qkv   = (const float*)d_in[3];
    const float* w_dense = (const float*)d_in[4];
    const float* b_dense = (const float*)d_in[5];
    float* out = (float*)d_out;

    void *hs_h, *wqkv_h, *wd_h, *ctx_h;
    cudaGetSymbolAddress(&hs_h, g_hs);
    cudaGetSymbolAddress(&wqkv_h, g_wqkv);
    cudaGetSymbolAddress(&wd_h, g_wd);
    cudaGetSymbolAddress(&ctx_h, g_ctx);

    cudaFuncSetAttribute(gemm_f16, cudaFuncAttributeMaxDynamicSharedMemorySize, GEMM_SMEM);
    cudaFuncSetAttribute(attn_f16, cudaFuncAttributeMaxDynamicSharedMemorySize, ATTN_SMEM);

    // 0) fp32 -> fp16 conversions
    f2h_kernel<<<(MROWS * HH) / (256 * 8), 256>>>(hs, (__half*)hs_h, MROWS * HH);
    f2h_kernel<<<(HH * QKV_N) / (256 * 8), 256>>>(w_qkv, (__half*)wqkv_h, HH * QKV_N);
    f2h_kernel<<<(HH * HH) / (256 * 8), 256>>>(w_dense, (__half*)wd_h, HH * HH);

    // 1) QKV projection with head-layout scatter (q pre-scaled)
    dim3 g1(QKV_N / 128, MROWS / 128);   // (24, 32)
    gemm_f16<<<g1, 256, GEMM_SMEM>>>((const __half*)hs_h, (const __half*)wqkv_h,
                                     b_qkv, nullptr, QKV_N, HH, 1);

    // 2) Causal flash attention
    dim3 g2(SS / 64, BB * NH);           // (32, 32)
    attn_f16<<<g2, 128, ATTN_SMEM>>>();

    // 3) Output projection
    dim3 g3(HH / 128, MROWS / 128);      // (8, 32)
    gemm_f16<<<g3, 256, GEMM_SMEM>>>((const __half*)ctx_h, (const __half*)wd_h,
                                     b_dense, out, HH, HH, 0);
}